// round 16
// baseline (speedup 1.0000x reference)
#include <cuda_runtime.h>
#include <cuda_bf16.h>

// Shapes (fixed by the problem)
#define B_  16
#define N_  1024
#define L_  7
#define D_  512
#define H_  8
#define HD_ 64
#define BN_ (B_ * N_)   // 16384

// attention tiling
#define QR_   64        // q rows per block
#define QSTR  68        // Qt row stride (floats); 272B => LDS.128-aligned for all d
#define KSTR  66        // Kt row stride
#define PSTR  68        // Ps row stride; 272B => LDS.128-aligned
#define ATTN_SMEM_FLOATS (64 * QSTR + 64 * PSTR + 64 * 64)   // 12800
#define ATTN_SMEM_BYTES  (ATTN_SMEM_FLOATS * 4)              // 51200

// ---------------- scratch (device globals; no cudaMalloc allowed) ----------
__device__ __align__(16) float g_agg[BN_ * D_];
__device__ __align__(16) float g_Qb [BN_ * D_];
__device__ __align__(16) float g_Kb [BN_ * D_];
__device__ __align__(16) float g_Vb [BN_ * D_];
__device__ __align__(16) float g_att[BN_ * D_];
__device__ __align__(16) float g_Ob [BN_ * D_];
// bf16 split buffers (hi + lo)
__device__ __align__(16) __nv_bfloat16 g_curh[BN_ * D_], g_curl[BN_ * D_];
__device__ __align__(16) __nv_bfloat16 g_aggh[BN_ * D_], g_aggl[BN_ * D_];
__device__ __align__(16) __nv_bfloat16 g_abh [BN_ * D_], g_abl [BN_ * D_];
__device__ __align__(16) __nv_bfloat16 g_wh[4 * D_ * D_], g_wl[4 * D_ * D_];

// ---------------- packed fp32x2 helpers (attention only) -------------------
__device__ __forceinline__ void fma2(unsigned long long& d,
                                     unsigned long long a,
                                     unsigned long long b) {
    asm("fma.rn.f32x2 %0, %1, %2, %0;" : "+l"(d) : "l"(a), "l"(b));
}
__device__ __forceinline__ void mul2(unsigned long long& d, unsigned long long a) {
    asm("mul.rn.f32x2 %0, %0, %1;" : "+l"(d) : "l"(a));
}
__device__ __forceinline__ unsigned long long bcast2f(float x) {
    unsigned long long r;
    asm("mov.b64 %0, {%1, %1};" : "=l"(r) : "f"(x));
    return r;
}
__device__ __forceinline__ unsigned long long pack2f(float x, float y) {
    unsigned long long r;
    asm("mov.b64 %0, {%1, %2};" : "=l"(r) : "f"(x), "f"(y));
    return r;
}
__device__ __forceinline__ float2 unpack2(unsigned long long v) {
    float2 r;
    asm("mov.b64 {%0, %1}, %2;" : "=f"(r.x), "=f"(r.y) : "l"(v));
    return r;
}

// ---------------- warp reductions ------------------------------------------
__device__ __forceinline__ float warpMax(float v) {
#pragma unroll
    for (int o = 16; o > 0; o >>= 1) v = fmaxf(v, __shfl_xor_sync(0xffffffffu, v, o));
    return v;
}
__device__ __forceinline__ float warpSum(float v) {
#pragma unroll
    for (int o = 16; o > 0; o >>= 1) v += __shfl_xor_sync(0xffffffffu, v, o);
    return v;
}

// ---------------- mma.sync m16n8k16 bf16 helper ----------------------------
__device__ __forceinline__ void mma_bf16(float* d, const unsigned* a, const unsigned* b) {
    asm volatile(
        "mma.sync.aligned.m16n8k16.row.col.f32.bf16.bf16.f32 "
        "{%0,%1,%2,%3}, {%4,%5,%6,%7}, {%8,%9}, {%0,%1,%2,%3};"
        : "+f"(d[0]), "+f"(d[1]), "+f"(d[2]), "+f"(d[3])
        : "r"(a[0]), "r"(a[1]), "r"(a[2]), "r"(a[3]), "r"(b[0]), "r"(b[1]));
}

// ---------------- Kernel 1: lag softmax + aggregation ----------------------
__global__ void __launch_bounds__(256)
lag_agg_kernel(const float* __restrict__ lf, const float* __restrict__ lw,
               float* __restrict__ outp)
{
    float wv[L_];
    float mx = lw[0];
#pragma unroll
    for (int l = 1; l < L_; l++) mx = fmaxf(mx, lw[l]);
    float sm = 0.f;
#pragma unroll
    for (int l = 0; l < L_; l++) { wv[l] = __expf(lw[l] - mx); sm += wv[l]; }
    float inv = 1.f / sm;
#pragma unroll
    for (int l = 0; l < L_; l++) wv[l] *= inv;

    int idx = blockIdx.x * 256 + threadIdx.x;
    int bn  = idx >> 7;
    int d4  = (idx & 127) * 4;
    const float* base = lf + (long)bn * (L_ * D_) + d4;
    float4 acc = make_float4(0.f, 0.f, 0.f, 0.f);
#pragma unroll
    for (int l = 0; l < L_; l++) {
        float4 v = *(const float4*)(base + l * D_);
        acc.x = fmaf(wv[l], v.x, acc.x);
        acc.y = fmaf(wv[l], v.y, acc.y);
        acc.z = fmaf(wv[l], v.z, acc.z);
        acc.w = fmaf(wv[l], v.w, acc.w);
    }
    *(float4*)(outp + (long)bn * D_ + d4) = acc;
}

// ---------------- split kernels: fp32 -> bf16 hi + lo ----------------------
__device__ __forceinline__ void split4(float4 v, __nv_bfloat16* hi,
                                       __nv_bfloat16* lo, long i4) {
    __nv_bfloat16 h0 = __float2bfloat16_rn(v.x);
    __nv_bfloat16 h1 = __float2bfloat16_rn(v.y);
    __nv_bfloat16 h2 = __float2bfloat16_rn(v.z);
    __nv_bfloat16 h3 = __float2bfloat16_rn(v.w);
    __nv_bfloat16 l0 = __float2bfloat16_rn(v.x - __bfloat162float(h0));
    __nv_bfloat16 l1 = __float2bfloat16_rn(v.y - __bfloat162float(h1));
    __nv_bfloat16 l2 = __float2bfloat16_rn(v.z - __bfloat162float(h2));
    __nv_bfloat16 l3 = __float2bfloat16_rn(v.w - __bfloat162float(h3));
    ((__nv_bfloat162*)hi)[i4 * 2]     = __nv_bfloat162(h0, h1);
    ((__nv_bfloat162*)hi)[i4 * 2 + 1] = __nv_bfloat162(h2, h3);
    ((__nv_bfloat162*)lo)[i4 * 2]     = __nv_bfloat162(l0, l1);
    ((__nv_bfloat162*)lo)[i4 * 2 + 1] = __nv_bfloat162(l2, l3);
}

// big arrays (grid.x * 256 threads, one float4 each)
__global__ void __launch_bounds__(256)
split_kernel(const float* __restrict__ x, __nv_bfloat16* __restrict__ hi,
             __nv_bfloat16* __restrict__ lo)
{
    long i = (long)blockIdx.x * 256 + threadIdx.x;
    split4(((const float4*)x)[i], hi, lo, i);
}

// 4 weights in one launch: grid (256, 4)
__global__ void __launch_bounds__(256)
splitw_kernel(const float* __restrict__ Wq, const float* __restrict__ Wk,
              const float* __restrict__ Wv, const float* __restrict__ Wo,
              __nv_bfloat16* __restrict__ wh, __nv_bfloat16* __restrict__ wl)
{
    int z = blockIdx.y;
    const float* W = (z == 0) ? Wq : (z == 1) ? Wk : (z == 2) ? Wv : Wo;
    long i = (long)blockIdx.x * 256 + threadIdx.x;       // < D_*D_/4
    long off4 = (long)z * (D_ * D_ / 4);
    split4(((const float4*)W)[i], wh, wl, off4 + i);
}

// ---------------- tensor-core GEMM: C = A @ W^T + bias ---------------------
// Split bf16, 3 passes: Ahi*Whi + Ahi*Wlo + Alo*Whi (lo*lo dropped, ~4e-6).
// Block 128x128, 256 thr = 8 warps (2x4), warp tile 64x32 = 4x4 m16n8k16.
// Fragments loaded directly from global per the PTX ISA lane tables
// (A row-major: a0=[g][2t],a1=[g+8][2t],a2=[g][2t+8],a3=[g+8][2t+8];
//  B col (=W[n][k] k-contig): b0=W[g][2t], b1=W[g][2t+8]; C: c01=[g][2t],c23=[g+8][2t]).
__device__ __forceinline__ void
mma_gemm_body(const __nv_bfloat16* __restrict__ Ah, const __nv_bfloat16* __restrict__ Al,
              const __nv_bfloat16* __restrict__ Wh, const __nv_bfloat16* __restrict__ Wl,
              const float* __restrict__ bias, float* __restrict__ C,
              int brow, int bcol)
{
    const int tid = threadIdx.x;
    const int w = tid >> 5, l = tid & 31;
    const int wm = w >> 2, wn = w & 3;          // 2 x 4 warp grid
    const int g = l >> 2, t = l & 3;
    const int mrow = brow + wm * 64;            // warp m origin
    const int ncol = bcol + wn * 32;            // warp n origin

    float acc[4][4][4];
#pragma unroll
    for (int mt = 0; mt < 4; mt++)
#pragma unroll
        for (int nt = 0; nt < 4; nt++)
#pragma unroll
            for (int r = 0; r < 4; r++) acc[mt][nt][r] = 0.f;

#pragma unroll 1
    for (int k0 = 0; k0 < D_; k0 += 16) {
        unsigned ahi[4][4], bhi[4][2];
#pragma unroll
        for (int mt = 0; mt < 4; mt++) {
            long r0 = (long)(mrow + mt * 16 + g) * D_ + k0 + 2 * t;
            ahi[mt][0] = *(const unsigned*)(Ah + r0);
            ahi[mt][1] = *(const unsigned*)(Ah + r0 + 8 * D_);
            ahi[mt][2] = *(const unsigned*)(Ah + r0 + 8);
            ahi[mt][3] = *(const unsigned*)(Ah + r0 + 8 * D_ + 8);
        }
#pragma unroll
        for (int nt = 0; nt < 4; nt++) {
            long c0 = (long)(ncol + nt * 8 + g) * D_ + k0 + 2 * t;
            bhi[nt][0] = *(const unsigned*)(Wh + c0);
            bhi[nt][1] = *(const unsigned*)(Wh + c0 + 8);
        }
        // pass 1: hi * hi
#pragma unroll
        for (int mt = 0; mt < 4; mt++)
#pragma unroll
            for (int nt = 0; nt < 4; nt++)
                mma_bf16(acc[mt][nt], ahi[mt], bhi[nt]);
        // pass 2: lo * hi
        {
            unsigned alo[4][4];
#pragma unroll
            for (int mt = 0; mt < 4; mt++) {
                long r0 = (long)(mrow + mt * 16 + g) * D_ + k0 + 2 * t;
                alo[mt][0] = *(const unsigned*)(Al + r0);
                alo[mt][1] = *(const unsigned*)(Al + r0 + 8 * D_);
                alo[mt][2] = *(const unsigned*)(Al + r0 + 8);
                alo[mt][3] = *(const unsigned*)(Al + r0 + 8 * D_ + 8);
            }
#pragma unroll
            for (int mt = 0; mt < 4; mt++)
#pragma unroll
                for (int nt = 0; nt < 4; nt++)
                    mma_bf16(acc[mt][nt], alo[mt], bhi[nt]);
        }
        // pass 3: hi * lo
        {
            unsigned blo[4][2];
#pragma unroll
            for (int nt = 0; nt < 4; nt++) {
                long c0 = (long)(ncol + nt * 8 + g) * D_ + k0 + 2 * t;
                blo[nt][0] = *(const unsigned*)(Wl + c0);
                blo[nt][1] = *(const unsigned*)(Wl + c0 + 8);
            }
#pragma unroll
            for (int mt = 0; mt < 4; mt++)
#pragma unroll
                for (int nt = 0; nt < 4; nt++)
                    mma_bf16(acc[mt][nt], ahi[mt], blo[nt]);
        }
    }

    // epilogue: += bias, store fp32
#pragma unroll
    for (int nt = 0; nt < 4; nt++) {
        float2 bv = *(const float2*)(bias + ncol + nt * 8 + 2 * t);
#pragma unroll
        for (int mt = 0; mt < 4; mt++) {
            long o0 = (long)(mrow + mt * 16 + g) * D_ + ncol + nt * 8 + 2 * t;
            *(float2*)(C + o0) =
                make_float2(acc[mt][nt][0] + bv.x, acc[mt][nt][1] + bv.y);
            *(float2*)(C + o0 + 8 * D_) =
                make_float2(acc[mt][nt][2] + bv.x, acc[mt][nt][3] + bv.y);
        }
    }
}

// fused QKV (gridDim.z = 3): z selects {cur,Wq,bq,Qb}/{agg,Wk,bk,Kb}/{agg,Wv,bv,Vb}
__global__ void __launch_bounds__(256)
qkv_mma_kernel(const __nv_bfloat16* __restrict__ curh, const __nv_bfloat16* __restrict__ curl,
               const __nv_bfloat16* __restrict__ aggh, const __nv_bfloat16* __restrict__ aggl,
               const __nv_bfloat16* __restrict__ wh, const __nv_bfloat16* __restrict__ wl,
               const float* __restrict__ bq, const float* __restrict__ bk,
               const float* __restrict__ bv,
               float* __restrict__ Qb, float* __restrict__ Kb, float* __restrict__ Vb)
{
    const int z = blockIdx.z;
    const __nv_bfloat16* Ah = (z == 0) ? curh : aggh;
    const __nv_bfloat16* Al = (z == 0) ? curl : aggl;
    const __nv_bfloat16* Wh = wh + (long)z * D_ * D_;
    const __nv_bfloat16* Wl = wl + (long)z * D_ * D_;
    const float* bias = (z == 0) ? bq : (z == 1) ? bk : bv;
    float* C = (z == 0) ? Qb : (z == 1) ? Kb : Vb;
    mma_gemm_body(Ah, Al, Wh, Wl, bias, C, blockIdx.y << 7, blockIdx.x << 7);
}

// single GEMM (Wo projection; weight slot 3)
__global__ void __launch_bounds__(256)
wo_mma_kernel(const __nv_bfloat16* __restrict__ abh, const __nv_bfloat16* __restrict__ abl,
              const __nv_bfloat16* __restrict__ wh, const __nv_bfloat16* __restrict__ wl,
              const float* __restrict__ bo, float* __restrict__ Ob)
{
    mma_gemm_body(abh, abl, wh + 3L * D_ * D_, wl + 3L * D_ * D_, bo, Ob,
                  blockIdx.y << 7, blockIdx.x << 7);
}

// ---------------- Kernel 3: flash attention, 8-rows-per-warp f32x2 ---------
// (unchanged from the measured 1769us version)
__global__ void __launch_bounds__(256)
attn_kernel(const float* __restrict__ Qg, const float* __restrict__ Kg,
            const float* __restrict__ Vg, const float* __restrict__ adj,
            float* __restrict__ Og)
{
    extern __shared__ __align__(16) float smbuf[];
    float* Qt   = smbuf;                              // [64 d][QSTR]
    float* KtPs = smbuf + 64 * QSTR;                  // Kt[d][KSTR] | Ps[c][PSTR]
    float* Vs   = smbuf + 64 * QSTR + 64 * PSTR;      // [c][64]

    const int tid = threadIdx.x;
    const int g = tid >> 5, l = tid & 31;
    const int b = blockIdx.y >> 3, h = blockIdx.y & 7;
    const int q0 = blockIdx.x * QR_;

    const float* Qbase = Qg + ((long)(b * N_ + q0) * D_) + h * HD_;
#pragma unroll
    for (int j = 0; j < 4; j++) {
        int fi = tid + j * 256;
        int r = fi >> 4, f4 = (fi & 15) * 4;
        float4 q = *(const float4*)(Qbase + (long)r * D_ + f4);
        Qt[(f4 + 0) * QSTR + r] = q.x * 0.125f;
        Qt[(f4 + 1) * QSTR + r] = q.y * 0.125f;
        Qt[(f4 + 2) * QSTR + r] = q.z * 0.125f;
        Qt[(f4 + 3) * QSTR + r] = q.w * 0.125f;
    }

    unsigned long long o2[4][2] = {{0ull,0ull},{0ull,0ull},{0ull,0ull},{0ull,0ull}};
    float mrow[8], lsum[8];
#pragma unroll
    for (int r = 0; r < 8; r++) { mrow[r] = -1e30f; lsum[r] = 0.f; }

#pragma unroll 1
    for (int t = 0; t < 16; t++) {
        const int c0 = t * 64;
        __syncthreads();

        const float* Kbase = Kg + ((long)(b * N_ + c0) * D_) + h * HD_;
        const float* Vbase = Vg + ((long)(b * N_ + c0) * D_) + h * HD_;
#pragma unroll
        for (int j = 0; j < 4; j++) {
            int fi = tid + j * 256;
            int c = fi >> 4, f4 = (fi & 15) * 4;
            float4 kv = *(const float4*)(Kbase + (long)c * D_ + f4);
            KtPs[(f4 + 0) * KSTR + c] = kv.x;
            KtPs[(f4 + 1) * KSTR + c] = kv.y;
            KtPs[(f4 + 2) * KSTR + c] = kv.z;
            KtPs[(f4 + 3) * KSTR + c] = kv.w;
            float4 vv = *(const float4*)(Vbase + (long)c * D_ + f4);
            *(float4*)&Vs[c * 64 + f4] = vv;
        }
        __syncthreads();

        float2 ad[8];
#pragma unroll
        for (int rr = 0; rr < 8; rr++)
            ad[rr] = *(const float2*)(adj + (long)(q0 + 8 * g + rr) * N_ + c0 + 2 * l);

        unsigned long long s2[4][2] = {{0ull,0ull},{0ull,0ull},{0ull,0ull},{0ull,0ull}};
#pragma unroll
        for (int d = 0; d < 64; d++) {
            ulonglong2 qA = *(const ulonglong2*)&Qt[d * QSTR + 8 * g];
            ulonglong2 qB = *(const ulonglong2*)&Qt[d * QSTR + 8 * g + 4];
            float2 kk = *(const float2*)&KtPs[d * KSTR + 2 * l];
            unsigned long long k0 = bcast2f(kk.x);
            unsigned long long k1 = bcast2f(kk.y);
            fma2(s2[0][0], qA.x, k0); fma2(s2[0][1], qA.x, k1);
            fma2(s2[1][0], qA.y, k0); fma2(s2[1][1], qA.y, k1);
            fma2(s2[2][0], qB.x, k0); fma2(s2[2][1], qB.x, k1);
            fma2(s2[3][0], qB.y, k0); fma2(s2[3][1], qB.y, k1);
        }
        __syncthreads();

        float x0[8], x1[8];
#pragma unroll
        for (int p = 0; p < 4; p++) {
            float2 sa = unpack2(s2[p][0]);
            float2 sb = unpack2(s2[p][1]);
            x0[2 * p] = sa.x;     x1[2 * p] = sb.x;
            x0[2 * p + 1] = sa.y; x1[2 * p + 1] = sb.y;
        }
        float pr0[8], pr1[8], alv[8];
#pragma unroll
        for (int rr = 0; rr < 8; rr++) {
            float v0 = fmaf(ad[rr].x, 0.5f, x0[rr]);
            float v1 = fmaf(ad[rr].y, 0.5f, x1[rr]);
            float mx = warpMax(fmaxf(v0, v1));
            float mn = fmaxf(mrow[rr], mx);
            float al = __expf(mrow[rr] - mn);
            mrow[rr] = mn;
            float p0 = __expf(v0 - mn);
            float p1 = __expf(v1 - mn);
            float ps = warpSum(p0 + p1);
            lsum[rr] = lsum[rr] * al + ps;
            alv[rr] = al; pr0[rr] = p0; pr1[rr] = p1;
        }
#pragma unroll
        for (int p = 0; p < 4; p++) {
            unsigned long long ap = pack2f(alv[2 * p], alv[2 * p + 1]);
            mul2(o2[p][0], ap); mul2(o2[p][1], ap);
        }
#pragma unroll
        for (int p = 0; p < 4; p++) {
            *(float2*)&KtPs[(2 * l) * PSTR + 8 * g + 2 * p]     = make_float2(pr0[2 * p], pr0[2 * p + 1]);
            *(float2*)&KtPs[(2 * l + 1) * PSTR + 8 * g + 2 * p] = make_float2(pr1[2 * p], pr1[2 * p + 1]);
        }
        __syncwarp();

#pragma unroll
        for (int c = 0; c < 64; c++) {
            ulonglong2 pA = *(const ulonglong2*)&KtPs[c * PSTR + 8 * g];
            ulonglong2 pB = *(const ulonglong2*)&KtPs[c * PSTR + 8 * g + 4];
            float2 vv = *(const float2*)&Vs[c * 64 + 2 * l];
            unsigned long long v0 = bcast2f(vv.x);
            unsigned long long v1 = bcast2f(vv.y);
            fma2(o2[0][0], pA.x, v0); fma2(o2[0][1], pA.x, v1);
            fma2(o2[1][0], pA.y, v0); fma2(o2[1][1], pA.y, v1);
            fma2(o2[2][0], pB.x, v0); fma2(o2[2][1], pB.x, v1);
            fma2(o2[3][0], pB.y, v0); fma2(o2[3][1], pB.y, v1);
        }
    }

#pragma unroll
    for (int p = 0; p < 4; p++) {
        float2 oa = unpack2(o2[p][0]);
        float2 ob = unpack2(o2[p][1]);
        float ie = 1.f / lsum[2 * p];
        float io = 1.f / lsum[2 * p + 1];
        int re = q0 + 8 * g + 2 * p;
        *(float2*)(Og + ((long)(b * N_ + re) * D_) + h * HD_ + 2 * l)
            = make_float2(oa.x * ie, ob.x * ie);
        *(float2*)(Og + ((long)(b * N_ + re + 1) * D_) + h * HD_ + 2 * l)
            = make_float2(oa.y * io, ob.y * io);
    }
}

// ---------------- Kernel 4: residual + LayerNorm ---------------------------
__global__ void __launch_bounds__(128)
ln_kernel(const float* __restrict__ cur, const float* __restrict__ O,
          const float* __restrict__ gg, const float* __restrict__ bb,
          float* __restrict__ outp)
{
    __shared__ float red[8];
    const int row = blockIdx.x;
    const int t = threadIdx.x;
    const long base = (long)row * D_ + t * 4;

    float4 c4 = *(const float4*)(cur + base);
    float4 o4 = *(const float4*)(O + base);
    float4 x = make_float4(c4.x + o4.x, c4.y + o4.y, c4.z + o4.z, c4.w + o4.w);

    float s = x.x + x.y + x.z + x.w;
    float q = x.x * x.x + x.y * x.y + x.z * x.z + x.w * x.w;
    s = warpSum(s);
    q = warpSum(q);
    int wid = t >> 5;
    if ((t & 31) == 0) { red[wid] = s; red[4 + wid] = q; }
    __syncthreads();
    s = red[0] + red[1] + red[2] + red[3];
    q = red[4] + red[5] + red[6] + red[7];

    float mu = s * (1.f / D_);
    float var = q * (1.f / D_) - mu * mu;
    float rs = rsqrtf(var + 1e-5f);

    float4 g4 = *(const float4*)(gg + t * 4);
    float4 b4 = *(const float4*)(bb + t * 4);
    float4 y;
    y.x = (x.x - mu) * rs * g4.x + b4.x;
    y.y = (x.y - mu) * rs * g4.y + b4.y;
    y.z = (x.z - mu) * rs * g4.z + b4.z;
    y.w = (x.w - mu) * rs * g4.w + b4.w;
    *(float4*)(outp + base) = y;
}

// ---------------- launcher -------------------------------------------------
extern "C" void kernel_launch(void* const* d_in, const int* in_sizes, int n_in,
                              void* d_out, int out_size)
{
    const float* cur  = (const float*)d_in[0];
    const float* lf   = (const float*)d_in[1];
    const float* lw   = (const float*)d_in[2];
    const float* Wq   = (const float*)d_in[3];
    const float* bq   = (const float*)d_in[4];
    const float* Wk   = (const float*)d_in[5];
    const float* bk   = (const float*)d_in[6];
    const float* Wv   = (const float*)d_in[7];
    const float* bv   = (const float*)d_in[8];
    const float* Wo   = (const float*)d_in[9];
    const float* bo   = (const float*)d_in[10];
    const float* adj  = (const float*)d_in[11];
    const float* lng  = (const float*)d_in[12];
    const float* lnb  = (const float*)d_in[13];
    float* outp = (float*)d_out;

    float *agg, *Qb, *Kb, *Vb, *Ab, *Ob;
    cudaGetSymbolAddress((void**)&agg, g_agg);
    cudaGetSymbolAddress((void**)&Qb,  g_Qb);
    cudaGetSymbolAddress((void**)&Kb,  g_Kb);
    cudaGetSymbolAddress((void**)&Vb,  g_Vb);
    cudaGetSymbolAddress((void**)&Ab,  g_att);
    cudaGetSymbolAddress((void**)&Ob,  g_Ob);
    __nv_bfloat16 *curh, *curl, *aggh, *aggl, *abh, *abl, *wh, *wl;
    cudaGetSymbolAddress((void**)&curh, g_curh);
    cudaGetSymbolAddress((void**)&curl, g_curl);
    cudaGetSymbolAddress((void**)&aggh, g_aggh);
    cudaGetSymbolAddress((void**)&aggl, g_aggl);
    cudaGetSymbolAddress((void**)&abh,  g_abh);
    cudaGetSymbolAddress((void**)&abl,  g_abl);
    cudaGetSymbolAddress((void**)&wh,   g_wh);
    cudaGetSymbolAddress((void**)&wl,   g_wl);

    cudaFuncSetAttribute(attn_kernel,
                         cudaFuncAttributeMaxDynamicSharedMemorySize,
                         ATTN_SMEM_BYTES);

    const int BIG4 = (BN_ * D_ / 4) / 256;   // 8192 blocks

    // 1) lag-weighted aggregation
    lag_agg_kernel<<<BN_ * D_ / 4 / 256, 256>>>(lf, lw, agg);

    // 2) splits: cur, agg, weights
    split_kernel<<<BIG4, 256>>>(cur, curh, curl);
    split_kernel<<<BIG4, 256>>>(agg, aggh, aggl);
    dim3 wgrid((D_ * D_ / 4) / 256, 4);
    splitw_kernel<<<wgrid, 256>>>(Wq, Wk, Wv, Wo, wh, wl);

    // 3) fused Q,K,V projections (tensor cores)
    dim3 qkvgrid(D_ / 128, BN_ / 128, 3);
    qkv_mma_kernel<<<qkvgrid, 256>>>(curh, curl, aggh, aggl, wh, wl,
                                     bq, bk, bv, Qb, Kb, Vb);

    // 4) attention with adjacency bias
    dim3 agrid(N_ / QR_, B_ * H_);
    attn_kernel<<<agrid, 256, ATTN_SMEM_BYTES>>>(Qb, Kb, Vb, adj, Ab);

    // 5) output projection (tensor cores)
    split_kernel<<<BIG4, 256>>>(Ab, abh, abl);
    dim3 ggrid(D_ / 128, BN_ / 128);
    wo_mma_kernel<<<ggrid, 256>>>(abh, abl, wh, wl, bo, Ob);

    // 6) residual + layernorm
    ln_kernel<<<BN_, 128>>>(cur, Ob, lng, lnb, outp);
}